// round 16
// baseline (speedup 1.0000x reference)
#include <cuda_runtime.h>

#define IN_   26
#define H1_   64
#define H2_   32
#define T_    1000
#define TC_   100
#define ROWS_ 4
#define THREADS_ 384

#define L2E_      1.4426950408889634f
#define TWO_L2E_  2.8853900817779268f

typedef unsigned long long u64;

__device__ __forceinline__ void fma2(u64 &d, u64 a, u64 b) {
    asm("fma.rn.f32x2 %0, %1, %2, %0;" : "+l"(d) : "l"(a), "l"(b));
}
__device__ __forceinline__ float lo32(u64 v){ return __uint_as_float((unsigned)v); }
__device__ __forceinline__ float hi32(u64 v){ return __uint_as_float((unsigned)(v >> 32)); }
__device__ __forceinline__ u64 packf(float lo, float hi){
    return ((u64)__float_as_uint(hi) << 32) | (u64)__float_as_uint(lo);
}
__device__ __forceinline__ float ex2a(float x){ float r; asm("ex2.approx.f32 %0, %1;" : "=f"(r) : "f"(x)); return r; }
__device__ __forceinline__ float rcpa(float x){ float r; asm("rcp.approx.f32 %0, %1;" : "=f"(r) : "f"(x)); return r; }
__device__ __forceinline__ float tanh_true(float c) {
    float u = ex2a(fminf(TWO_L2E_ * c, 50.0f));
    return (u - 1.0f) * rcpa(u + 1.0f);
}
// sigmoid: no clamp needed — ex2(+inf)=inf, rcp(inf)=0 saturates exactly;
// tanh keeps its clamp (inf-1 -> NaN otherwise).
__device__ __forceinline__ float gate_act(float t, bool isg) {
    float u = ex2a(isg ? fminf(2.0f * t, 50.0f) : -t);
    return isg ? (u - 1.0f) * rcpa(u + 1.0f) : rcpa(1.0f + u);
}

// smem layout (floats)
__shared__ float xs[ROWS_ * TC_ * 28];   // [r][tt][28]  (44.8 KB)
__shared__ float h1s[2 * ROWS_ * 68];    // [buf][r][68] (64 used)
__shared__ float h2s[2 * ROWS_ * 36];    // [buf][r][36] (32 used)
__shared__ float sfc[64];                // FC1 intermediates [r][16]

__global__ void __launch_bounds__(THREADS_, 1) audiolstm_kernel(
    const float* __restrict__ x,
    const float* __restrict__ w_ih1, const float* __restrict__ w_hh1,
    const float* __restrict__ b_ih1, const float* __restrict__ b_hh1,
    const float* __restrict__ w_ih2, const float* __restrict__ w_hh2,
    const float* __restrict__ b_ih2, const float* __restrict__ b_hh2,
    const float* __restrict__ w_fc1, const float* __restrict__ b_fc1,
    const float* __restrict__ w_fc2, const float* __restrict__ b_fc2,
    float* __restrict__ out)
{
    const int tid  = threadIdx.x;
    const int row0 = blockIdx.x * ROWS_;
    const int lane4 = tid & 3;              // gate index within unit quad
    const bool p1 = (tid < 256);

    // ---- register-resident weights, PRESCALED by log2e ----
    u64 wu[48];
    float biasv;
    if (p1) {
        const int G = tid >> 2;                 // LSTM1 unit 0..63
        const int row = lane4 * 64 + G;         // gate row in [0,256)
        const float* wi = w_ih1 + row * IN_;
        const float* wh = w_hh1 + row * H1_;
#pragma unroll
        for (int p = 0; p < 13; ++p) wu[p] = packf(wi[2*p] * L2E_, wi[2*p+1] * L2E_);
        wu[13] = 0ull;
#pragma unroll
        for (int p = 0; p < 32; ++p) wu[14+p] = packf(wh[2*p] * L2E_, wh[2*p+1] * L2E_);
        wu[46] = 0ull; wu[47] = 0ull;
        biasv = (b_ih1[row] + b_hh1[row]) * L2E_;
    } else {
        const int J = (tid - 256) >> 2;         // LSTM2 unit 0..31
        const int row = lane4 * 32 + J;         // gate row in [0,128)
        const float* wi = w_ih2 + row * H1_;
        const float* wh = w_hh2 + row * H2_;
#pragma unroll
        for (int p = 0; p < 32; ++p) wu[p] = packf(wi[2*p] * L2E_, wi[2*p+1] * L2E_);
#pragma unroll
        for (int p = 0; p < 16; ++p) wu[32+p] = packf(wh[2*p] * L2E_, wh[2*p+1] * L2E_);
        biasv = (b_ih2[row] + b_hh2[row]) * L2E_;
    }
    const u64 bias_u = (u64)__float_as_uint(biasv);
    const int unitG = p1 ? (tid >> 2) : ((tid - 256) >> 2);
    const bool isg = (lane4 == 2);

    for (int i = tid; i < 2 * ROWS_ * 68; i += THREADS_) h1s[i] = 0.0f;
    for (int i = tid; i < 2 * ROWS_ * 36; i += THREADS_) h2s[i] = 0.0f;

    float cst = 0.0f;
    int pb = 0;

    for (int tile = 0; tile < T_ / TC_; ++tile) {
        for (int idx = tid; idx < ROWS_ * 28 * TC_; idx += THREADS_) {
            int rr = idx / (28 * TC_);
            int rem = idx - rr * (28 * TC_);
            int i  = rem / TC_, tt = rem - i * TC_;
            float v = 0.0f;
            if (i < IN_) v = x[((row0 + rr) * IN_ + i) * T_ + tile * TC_ + tt];
            xs[(rr * TC_ + tt) * 28 + i] = v;
        }
        __syncthreads();

        for (int tt = 0; tt < TC_; ++tt) {
            if (p1) {
                // ---------- LSTM1: dot products for 4 rows, dual accumulators ----------
                float a[4];
#pragma unroll
                for (int r = 0; r < 4; ++r) {
                    u64 accA = bias_u;   // x-part + h[0..7]
                    u64 accB = 0ull;     // h[8..63]
                    const ulonglong2* xp = (const ulonglong2*)(xs + (r * TC_ + tt) * 28);
#pragma unroll
                    for (int p = 0; p < 7; ++p) {
                        ulonglong2 v = xp[p];
                        fma2(accA, wu[2*p],   v.x);
                        fma2(accA, wu[2*p+1], v.y);
                    }
                    const ulonglong2* hp = (const ulonglong2*)(h1s + (pb * ROWS_ + r) * 68);
#pragma unroll
                    for (int p = 0; p < 4; ++p) {
                        ulonglong2 v = hp[p];
                        fma2(accA, wu[14 + 2*p], v.x);
                        fma2(accA, wu[15 + 2*p], v.y);
                    }
#pragma unroll
                    for (int p = 4; p < 16; ++p) {
                        ulonglong2 v = hp[p];
                        fma2(accB, wu[14 + 2*p], v.x);
                        fma2(accB, wu[15 + 2*p], v.y);
                    }
                    float t = (lo32(accA) + hi32(accA)) + (lo32(accB) + hi32(accB));
                    a[r] = gate_act(t, isg);
                }
                { // 4x4 quad transpose (bfly)
                    float e0 = __shfl_xor_sync(0xffffffffu, (lane4 & 2) ? a[0] : a[2], 2, 4);
                    float e1 = __shfl_xor_sync(0xffffffffu, (lane4 & 2) ? a[1] : a[3], 2, 4);
                    if (lane4 & 2) { a[0] = e0; a[1] = e1; } else { a[2] = e0; a[3] = e1; }
                    float f0 = __shfl_xor_sync(0xffffffffu, (lane4 & 1) ? a[0] : a[1], 1, 4);
                    float f1 = __shfl_xor_sync(0xffffffffu, (lane4 & 1) ? a[2] : a[3], 1, 4);
                    if (lane4 & 1) { a[0] = f0; a[2] = f1; } else { a[1] = f0; a[3] = f1; }
                }
                cst = fmaf(a[1], cst, a[0] * a[2]);
                float hv = a[3] * tanh_true(cst);
                h1s[((pb ^ 1) * ROWS_ + lane4) * 68 + unitG] = hv;
            }
            __syncthreads();
            if (!p1) {
                // ---------- LSTM2 (overlaps next step's LSTM1), dual accumulators ----------
                float a[4];
#pragma unroll
                for (int r = 0; r < 4; ++r) {
                    u64 accA = bias_u;   // h1[0..31]
                    u64 accB = 0ull;     // h1[32..63] + h2[0..31]
                    const ulonglong2* hp1 = (const ulonglong2*)(h1s + ((pb ^ 1) * ROWS_ + r) * 68);
#pragma unroll
                    for (int p = 0; p < 8; ++p) {
                        ulonglong2 v = hp1[p];
                        fma2(accA, wu[2*p],   v.x);
                        fma2(accA, wu[2*p+1], v.y);
                    }
#pragma unroll
                    for (int p = 8; p < 16; ++p) {
                        ulonglong2 v = hp1[p];
                        fma2(accB, wu[2*p],   v.x);
                        fma2(accB, wu[2*p+1], v.y);
                    }
                    const ulonglong2* hp2 = (const ulonglong2*)(h2s + (pb * ROWS_ + r) * 36);
#pragma unroll
                    for (int p = 0; p < 8; ++p) {
                        ulonglong2 v = hp2[p];
                        fma2(accB, wu[32 + 2*p], v.x);
                        fma2(accB, wu[33 + 2*p], v.y);
                    }
                    float t = (lo32(accA) + hi32(accA)) + (lo32(accB) + hi32(accB));
                    a[r] = gate_act(t, isg);
                }
                {
                    float e0 = __shfl_xor_sync(0xffffffffu, (lane4 & 2) ? a[0] : a[2], 2, 4);
                    float e1 = __shfl_xor_sync(0xffffffffu, (lane4 & 2) ? a[1] : a[3], 2, 4);
                    if (lane4 & 2) { a[0] = e0; a[1] = e1; } else { a[2] = e0; a[3] = e1; }
                    float f0 = __shfl_xor_sync(0xffffffffu, (lane4 & 1) ? a[0] : a[1], 1, 4);
                    float f1 = __shfl_xor_sync(0xffffffffu, (lane4 & 1) ? a[2] : a[3], 1, 4);
                    if (lane4 & 1) { a[0] = f0; a[2] = f1; } else { a[1] = f0; a[3] = f1; }
                }
                cst = fmaf(a[1], cst, a[0] * a[2]);
                float hv = a[3] * tanh_true(cst);
                h2s[((pb ^ 1) * ROWS_ + lane4) * 36 + unitG] = hv;
            }
            pb ^= 1;
        }
    }

    __syncthreads();

    // ---------------- FC head (pb == 0 after 1000 flips; final h2 in h2s[0]) ----------------
    if (tid < 64) {
        int r = tid & 3, f = tid >> 2;
        const float* hrow = h2s + (pb * ROWS_ + r) * 36;
        float acc = b_fc1[f];
#pragma unroll
        for (int k = 0; k < H2_; ++k) acc = fmaf(hrow[k], w_fc1[f * H2_ + k], acc);
        sfc[r * 16 + f] = fmaxf(acc, 0.0f);
    }
    __syncthreads();
    if (tid < 40) {
        int r = tid & 3, o = tid >> 2;
        float acc = b_fc2[o];
#pragma unroll
        for (int k = 0; k < 16; ++k) acc = fmaf(sfc[r * 16 + k], w_fc2[o * 16 + k], acc);
        out[(row0 + r) * 10 + o] = acc;
    }
}

extern "C" void kernel_launch(void* const* d_in, const int* in_sizes, int n_in,
                              void* d_out, int out_size) {
    const float* x     = (const float*)d_in[0];
    const float* w_ih1 = (const float*)d_in[1];
    const float* w_hh1 = (const float*)d_in[2];
    const float* b_ih1 = (const float*)d_in[3];
    const float* b_hh1 = (const float*)d_in[4];
    const float* w_ih2 = (const float*)d_in[5];
    const float* w_hh2 = (const float*)d_in[6];
    const float* b_ih2 = (const float*)d_in[7];
    const float* b_hh2 = (const float*)d_in[8];
    const float* w_fc1 = (const float*)d_in[9];
    const float* b_fc1 = (const float*)d_in[10];
    const float* w_fc2 = (const float*)d_in[11];
    const float* b_fc2 = (const float*)d_in[12];
    float* out = (float*)d_out;

    int Bv = in_sizes[0] / (IN_ * T_);       // 512
    int grid = Bv / ROWS_;                   // 128 CTAs
    audiolstm_kernel<<<grid, THREADS_>>>(
        x, w_ih1, w_hh1, b_ih1, b_hh1,
        w_ih2, w_hh2, b_ih2, b_hh2,
        w_fc1, b_fc1, w_fc2, b_fc2, out);
}

// round 17
// speedup vs baseline: 1.0257x; 1.0257x over previous
#include <cuda_runtime.h>

#define IN_   26
#define H1_   64
#define H2_   32
#define T_    1000
#define TC_   50
#define ROWS_ 4
#define THREADS_ 384

#define L2E_      1.4426950408889634f
#define TWO_L2E_  2.8853900817779268f

typedef unsigned long long u64;

__device__ __forceinline__ void fma2(u64 &d, u64 a, u64 b) {
    asm("fma.rn.f32x2 %0, %1, %2, %0;" : "+l"(d) : "l"(a), "l"(b));
}
__device__ __forceinline__ float lo32(u64 v){ return __uint_as_float((unsigned)v); }
__device__ __forceinline__ float hi32(u64 v){ return __uint_as_float((unsigned)(v >> 32)); }
__device__ __forceinline__ u64 packf(float lo, float hi){
    return ((u64)__float_as_uint(hi) << 32) | (u64)__float_as_uint(lo);
}
__device__ __forceinline__ float ex2a(float x){ float r; asm("ex2.approx.f32 %0, %1;" : "=f"(r) : "f"(x)); return r; }
__device__ __forceinline__ float rcpa(float x){ float r; asm("rcp.approx.f32 %0, %1;" : "=f"(r) : "f"(x)); return r; }
__device__ __forceinline__ float tanh_true(float c) {
    float u = ex2a(fminf(TWO_L2E_ * c, 50.0f));
    return (u - 1.0f) * rcpa(u + 1.0f);
}
__device__ __forceinline__ float gate_act(float t, bool isg) {
    float arg = isg ? fminf(2.0f * t, 50.0f) : fminf(-t, 50.0f);
    float u = ex2a(arg);
    return isg ? (u - 1.0f) * rcpa(u + 1.0f) : rcpa(1.0f + u);
}

// smem layout (floats)
__shared__ float xs[ROWS_ * TC_ * 28];   // [r][tt][28]
__shared__ float h1s[2 * ROWS_ * 68];    // [buf][r][68] (64 used)
__shared__ float h2s[2 * ROWS_ * 36];    // [buf][r][36] (32 used)
__shared__ float sfc[64];                // FC1 intermediates [r][16]

__global__ void __launch_bounds__(THREADS_, 1) audiolstm_kernel(
    const float* __restrict__ x,
    const float* __restrict__ w_ih1, const float* __restrict__ w_hh1,
    const float* __restrict__ b_ih1, const float* __restrict__ b_hh1,
    const float* __restrict__ w_ih2, const float* __restrict__ w_hh2,
    const float* __restrict__ b_ih2, const float* __restrict__ b_hh2,
    const float* __restrict__ w_fc1, const float* __restrict__ b_fc1,
    const float* __restrict__ w_fc2, const float* __restrict__ b_fc2,
    float* __restrict__ out)
{
    const int tid  = threadIdx.x;
    const int row0 = blockIdx.x * ROWS_;
    const int lane4 = tid & 3;              // gate index within unit quad
    const bool p1 = (tid < 256);

    // ---- register-resident weights, PRESCALED by log2e ----
    u64 wu[48];
    float biasv;
    if (p1) {
        const int G = tid >> 2;                 // LSTM1 unit 0..63
        const int row = lane4 * 64 + G;         // gate row in [0,256)
        const float* wi = w_ih1 + row * IN_;
        const float* wh = w_hh1 + row * H1_;
#pragma unroll
        for (int p = 0; p < 13; ++p) wu[p] = packf(wi[2*p] * L2E_, wi[2*p+1] * L2E_);
        wu[13] = 0ull;
#pragma unroll
        for (int p = 0; p < 32; ++p) wu[14+p] = packf(wh[2*p] * L2E_, wh[2*p+1] * L2E_);
        wu[46] = 0ull; wu[47] = 0ull;
        biasv = (b_ih1[row] + b_hh1[row]) * L2E_;
    } else {
        const int J = (tid - 256) >> 2;         // LSTM2 unit 0..31
        const int row = lane4 * 32 + J;         // gate row in [0,128)
        const float* wi = w_ih2 + row * H1_;
        const float* wh = w_hh2 + row * H2_;
#pragma unroll
        for (int p = 0; p < 32; ++p) wu[p] = packf(wi[2*p] * L2E_, wi[2*p+1] * L2E_);
#pragma unroll
        for (int p = 0; p < 16; ++p) wu[32+p] = packf(wh[2*p] * L2E_, wh[2*p+1] * L2E_);
        biasv = (b_ih2[row] + b_hh2[row]) * L2E_;
    }
    const u64 bias_u = (u64)__float_as_uint(biasv);
    const int unitG = p1 ? (tid >> 2) : ((tid - 256) >> 2);
    const bool isg = (lane4 == 2);

    for (int i = tid; i < 2 * ROWS_ * 68; i += THREADS_) h1s[i] = 0.0f;
    for (int i = tid; i < 2 * ROWS_ * 36; i += THREADS_) h2s[i] = 0.0f;

    float cst = 0.0f;
    int pb = 0;

    for (int tile = 0; tile < T_ / TC_; ++tile) {
        for (int idx = tid; idx < ROWS_ * 28 * TC_; idx += THREADS_) {
            int rr = idx / (28 * TC_);
            int rem = idx - rr * (28 * TC_);
            int i  = rem / TC_, tt = rem - i * TC_;
            float v = 0.0f;
            if (i < IN_) v = x[((row0 + rr) * IN_ + i) * T_ + tile * TC_ + tt];
            xs[(rr * TC_ + tt) * 28 + i] = v;
        }
        __syncthreads();

        for (int tt = 0; tt < TC_; ++tt) {
            if (p1) {
                // ---------- LSTM1: dot products for 4 rows, dual accumulators ----------
                float a[4];
#pragma unroll
                for (int r = 0; r < 4; ++r) {
                    u64 accA = bias_u;   // x-part + h[0..7]
                    u64 accB = 0ull;     // h[8..63]
                    const ulonglong2* xp = (const ulonglong2*)(xs + (r * TC_ + tt) * 28);
#pragma unroll
                    for (int p = 0; p < 7; ++p) {
                        ulonglong2 v = xp[p];
                        fma2(accA, wu[2*p],   v.x);
                        fma2(accA, wu[2*p+1], v.y);
                    }
                    const ulonglong2* hp = (const ulonglong2*)(h1s + (pb * ROWS_ + r) * 68);
#pragma unroll
                    for (int p = 0; p < 4; ++p) {
                        ulonglong2 v = hp[p];
                        fma2(accA, wu[14 + 2*p], v.x);
                        fma2(accA, wu[15 + 2*p], v.y);
                    }
#pragma unroll
                    for (int p = 4; p < 16; ++p) {
                        ulonglong2 v = hp[p];
                        fma2(accB, wu[14 + 2*p], v.x);
                        fma2(accB, wu[15 + 2*p], v.y);
                    }
                    float t = (lo32(accA) + hi32(accA)) + (lo32(accB) + hi32(accB));
                    a[r] = gate_act(t, isg);
                }
                { // 4x4 quad transpose (bfly)
                    float e0 = __shfl_xor_sync(0xffffffffu, (lane4 & 2) ? a[0] : a[2], 2, 4);
                    float e1 = __shfl_xor_sync(0xffffffffu, (lane4 & 2) ? a[1] : a[3], 2, 4);
                    if (lane4 & 2) { a[0] = e0; a[1] = e1; } else { a[2] = e0; a[3] = e1; }
                    float f0 = __shfl_xor_sync(0xffffffffu, (lane4 & 1) ? a[0] : a[1], 1, 4);
                    float f1 = __shfl_xor_sync(0xffffffffu, (lane4 & 1) ? a[2] : a[3], 1, 4);
                    if (lane4 & 1) { a[0] = f0; a[2] = f1; } else { a[1] = f0; a[3] = f1; }
                }
                cst = fmaf(a[1], cst, a[0] * a[2]);
                float hv = a[3] * tanh_true(cst);
                h1s[((pb ^ 1) * ROWS_ + lane4) * 68 + unitG] = hv;
            }
            __syncthreads();
            if (!p1) {
                // ---------- LSTM2 (overlaps next step's LSTM1), dual accumulators ----------
                float a[4];
#pragma unroll
                for (int r = 0; r < 4; ++r) {
                    u64 accA = bias_u;   // h1[0..31]
                    u64 accB = 0ull;     // h1[32..63] + h2[0..31]
                    const ulonglong2* hp1 = (const ulonglong2*)(h1s + ((pb ^ 1) * ROWS_ + r) * 68);
#pragma unroll
                    for (int p = 0; p < 8; ++p) {
                        ulonglong2 v = hp1[p];
                        fma2(accA, wu[2*p],   v.x);
                        fma2(accA, wu[2*p+1], v.y);
                    }
#pragma unroll
                    for (int p = 8; p < 16; ++p) {
                        ulonglong2 v = hp1[p];
                        fma2(accB, wu[2*p],   v.x);
                        fma2(accB, wu[2*p+1], v.y);
                    }
                    const ulonglong2* hp2 = (const ulonglong2*)(h2s + (pb * ROWS_ + r) * 36);
#pragma unroll
                    for (int p = 0; p < 8; ++p) {
                        ulonglong2 v = hp2[p];
                        fma2(accB, wu[32 + 2*p], v.x);
                        fma2(accB, wu[33 + 2*p], v.y);
                    }
                    float t = (lo32(accA) + hi32(accA)) + (lo32(accB) + hi32(accB));
                    a[r] = gate_act(t, isg);
                }
                {
                    float e0 = __shfl_xor_sync(0xffffffffu, (lane4 & 2) ? a[0] : a[2], 2, 4);
                    float e1 = __shfl_xor_sync(0xffffffffu, (lane4 & 2) ? a[1] : a[3], 2, 4);
                    if (lane4 & 2) { a[0] = e0; a[1] = e1; } else { a[2] = e0; a[3] = e1; }
                    float f0 = __shfl_xor_sync(0xffffffffu, (lane4 & 1) ? a[0] : a[1], 1, 4);
                    float f1 = __shfl_xor_sync(0xffffffffu, (lane4 & 1) ? a[2] : a[3], 1, 4);
                    if (lane4 & 1) { a[0] = f0; a[2] = f1; } else { a[1] = f0; a[3] = f1; }
                }
                cst = fmaf(a[1], cst, a[0] * a[2]);
                float hv = a[3] * tanh_true(cst);
                h2s[((pb ^ 1) * ROWS_ + lane4) * 36 + unitG] = hv;
            }
            pb ^= 1;
        }
    }

    __syncthreads();

    // ---------------- FC head ----------------
    if (tid < 64) {
        int r = tid & 3, f = tid >> 2;
        const float* hrow = h2s + (pb * ROWS_ + r) * 36;
        float acc = b_fc1[f];
#pragma unroll
        for (int k = 0; k < H2_; ++k) acc = fmaf(hrow[k], w_fc1[f * H2_ + k], acc);
        sfc[r * 16 + f] = fmaxf(acc, 0.0f);
    }
    __syncthreads();
    if (tid < 40) {
        int r = tid & 3, o = tid >> 2;
        float acc = b_fc2[o];
#pragma unroll
        for (int k = 0; k < 16; ++k) acc = fmaf(sfc[r * 16 + k], w_fc2[o * 16 + k], acc);
        out[(row0 + r) * 10 + o] = acc;
    }
}

extern "C" void kernel_launch(void* const* d_in, const int* in_sizes, int n_in,
                              void* d_out, int out_size) {
    const float* x     = (const float*)d_in[0];
    const float* w_ih1 = (const float*)d_in[1];
    const float* w_hh1 = (const float*)d_in[2];
    const float* b_ih1 = (const float*)d_in[3];
    const float* b_hh1 = (const float*)d_in[4];
    const float* w_ih2 = (const float*)d_in[5];
    const float* w_hh2 = (const float*)d_in[6];
    const float* b_ih2 = (const float*)d_in[7];
    const float* b_hh2 = (const float*)d_in[8];
    const float* w_fc1 = (const float*)d_in[9];
    const float* b_fc1 = (const float*)d_in[10];
    const float* w_fc2 = (const float*)d_in[11];
    const float* b_fc2 = (const float*)d_in[12];
    float* out = (float*)d_out;

    int Bv = in_sizes[0] / (IN_ * T_);       // 512
    int grid = Bv / ROWS_;                   // 128 CTAs
    audiolstm_kernel<<<grid, THREADS_>>>(
        x, w_ih1, w_hh1, b_ih1, b_hh1,
        w_ih2, w_hh2, b_ih2, b_hh2,
        w_fc1, b_fc1, w_fc2, b_fc2, out);
}